// round 4
// baseline (speedup 1.0000x reference)
#include <cuda_runtime.h>

#define NNB   10
#define MAXN  100000
#define D     128
#define BN    32          // nodes per block (fused kernel)
#define JT    64          // output-column tile
#define EMPTYID 0xFFFFFFFFu

// Scratch: per-node 10 smallest edge ids (multiset; slot order nondeterministic).
__device__ unsigned g_slots[MAXN * NNB];

__global__ void k_init(int n) {
    int i = blockIdx.x * blockDim.x + threadIdx.x;
    if (i < n) g_slots[i] = EMPTYID;
}

// Concurrent bounded top-k-smallest insert via atomicMin cascade.
// Slots only decrease; the carried value is non-decreasing along the walk, so
// any value that falls off the end is >= every final kept value. Final multiset
// = the 10 smallest edge ids for the row == first 10 edges in original order.
__global__ void k_insert(const int* __restrict__ ei, int E) {
    int e = blockIdx.x * blockDim.x + threadIdx.x;
    if (e >= E) return;
    unsigned row = (unsigned)__ldg(&ei[e]);    // edge_index row (int32!)
    if (row >= MAXN) return;                   // guard: never trap
    unsigned* sl = g_slots + row * NNB;
    unsigned v = (unsigned)e;
    // Prune: stale slot[9] >= final slot[9]; edge ids unique, so v >= snapshot
    // implies v cannot be among the final 10 smallest.
    if (v >= sl[NNB - 1]) return;
#pragma unroll
    for (int s = 0; s < NNB; s++) {
        unsigned old = atomicMin(&sl[s], v);
        if (old == EMPTYID) return;    // landed in empty slot
        v = max(v, old);               // carry larger value rightward
    }
}

// Packed fp32x2 FMA (Blackwell): acc.lo += a.lo*b.lo; acc.hi += a.hi*b.hi
#define FMA2(acc, a, b) \
    asm("fma.rn.f32x2 %0, %1, %2, %0;" : "+l"(acc) : "l"(a), "l"(b))

#define UNPK(lo, hi, v) \
    asm("mov.b64 {%0, %1}, %2;" : "=r"(lo), "=r"(hi) : "l"(v))

// Compare-swap for the fixed sorting network (fully unrolled, register-resident)
#define CSWP(i, j) { unsigned mn = min(ids[i], ids[j]); \
                     unsigned mx = max(ids[i], ids[j]); \
                     ids[i] = mn; ids[j] = mx; }

// Fused: neighbor-mean aggregation + out = agg @ W^T + b.
// 256 threads. Phase 1: each warp gathers/means 4 nodes into sA.
// Phase 2: two j-tiles of 64; sW tile XOR-swizzled for conflict-free LDS.128.
// Thread tile: 4 nodes x 2 outputs, accumulated as f32x2 (even/odd k partials).
__global__ __launch_bounds__(256)
void k_agg_gemm(const float* __restrict__ x,
                const int* __restrict__ ei,
                const float* __restrict__ W,
                const float* __restrict__ b,
                float* __restrict__ out,
                int N, int E) {
    __shared__ float sA[BN * D];   // 16384 B
    __shared__ float sW[JT * D];   // 32768 B  (total static = 48 KB)

    int tid  = threadIdx.x;
    int lane = tid & 31;
    int warp = tid >> 5;           // 0..7
    int base = blockIdx.x * BN;

    const int* col = ei + E;       // second row of edge_index (int32)
    const float4* x4 = (const float4*)x;

    // ---- Phase 1: gather + mean (one warp per node, 4 nodes per warp) ----
#pragma unroll
    for (int i = 0; i < 4; i++) {
        int nl = warp * 4 + i;
        int node = base + nl;
        float4 acc = make_float4(0.f, 0.f, 0.f, 0.f);
        if (node < N) {
            unsigned ids[NNB];
            const unsigned* sl = g_slots + node * NNB;
#pragma unroll
            for (int s = 0; s < NNB; s++) ids[s] = __ldg(&sl[s]);  // uniform
            // Fixed 10-input sorting network -> deterministic summation order
            CSWP(0,5) CSWP(1,6) CSWP(2,7) CSWP(3,8) CSWP(4,9)
            CSWP(0,3) CSWP(1,4) CSWP(5,8) CSWP(6,9)
            CSWP(0,2) CSWP(3,6) CSWP(7,9)
            CSWP(0,1) CSWP(2,4) CSWP(5,7) CSWP(8,9)
            CSWP(1,2) CSWP(3,5) CSWP(4,6) CSWP(7,8)
            CSWP(1,3) CSWP(4,7) CSWP(2,5) CSWP(6,8)
            CSWP(2,3) CSWP(4,5) CSWP(6,7)
            CSWP(3,4) CSWP(5,6)
            int cnt = 0;
#pragma unroll
            for (int s = 0; s < NNB; s++) {
                unsigned id = ids[s];
                if (id != EMPTYID) {
                    int c = __ldg(&col[id]);              // warp-uniform
                    float4 v = __ldg(&x4[c * 32 + lane]); // coalesced 128B
                    acc.x += v.x; acc.y += v.y; acc.z += v.z; acc.w += v.w;
                    cnt++;
                }
            }
            if (cnt > 0) {
                float inv = 1.0f / (float)cnt;
                acc.x *= inv; acc.y *= inv; acc.z *= inv; acc.w *= inv;
            } else {
                acc = __ldg(&x4[node * 32 + lane]);       // no out-edges
            }
        }
        *(float4*)&sA[nl * D + lane * 4] = acc;
    }

    // ---- Phase 2: GEMM over two j-tiles of 64 columns ----
    const float4* W4 = (const float4*)W;
    int swz = (lane & 7) << 2;     // XOR swizzle offset for this thread's rows

#pragma unroll
    for (int jt = 0; jt < 2; jt++) {
        __syncthreads();           // sA ready (jt=0) / previous tile consumed
        // Stage W rows [jt*64, jt*64+64) into swizzled smem. 2048 float4 total.
#pragma unroll
        for (int r = 0; r < 8; r++) {
            int idx = tid + 256 * r;          // 0..2047
            int j   = idx >> 5;               // row in tile (32 float4 per row)
            int k4  = idx & 31;
            float4 w = __ldg(&W4[(jt * JT + j) * 32 + k4]);
            int cw = (k4 * 4) ^ ((j & 7) << 2);
            *(float4*)&sW[j * D + cw] = w;
        }
        __syncthreads();

        unsigned long long acc2[4][2];
#pragma unroll
        for (int i = 0; i < 4; i++) { acc2[i][0] = 0ull; acc2[i][1] = 0ull; }

#pragma unroll 8
        for (int k4 = 0; k4 < 32; k4++) {
            int kk = k4 * 4;
            int cw = kk ^ swz;     // (lane+32)&7 == lane&7 -> same swizzle
            ulonglong2 w0 = *(const ulonglong2*)&sW[lane * D + cw];
            ulonglong2 w1 = *(const ulonglong2*)&sW[(lane + 32) * D + cw];
#pragma unroll
            for (int i = 0; i < 4; i++) {
                ulonglong2 a = *(const ulonglong2*)&sA[(warp * 4 + i) * D + kk];
                FMA2(acc2[i][0], a.x, w0.x);
                FMA2(acc2[i][0], a.y, w0.y);
                FMA2(acc2[i][1], a.x, w1.x);
                FMA2(acc2[i][1], a.y, w1.y);
            }
        }

        float b0 = __ldg(&b[jt * JT + lane]);
        float b1 = __ldg(&b[jt * JT + lane + 32]);
#pragma unroll
        for (int i = 0; i < 4; i++) {
            int node = base + warp * 4 + i;
            if (node < N) {
                unsigned lo, hi;
                UNPK(lo, hi, acc2[i][0]);
                float r0 = __uint_as_float(lo) + __uint_as_float(hi) + b0;
                UNPK(lo, hi, acc2[i][1]);
                float r1 = __uint_as_float(lo) + __uint_as_float(hi) + b1;
                out[node * D + jt * JT + lane]      = r0;
                out[node * D + jt * JT + lane + 32] = r1;
            }
        }
    }
}

extern "C" void kernel_launch(void* const* d_in, const int* in_sizes, int n_in,
                              void* d_out, int out_size) {
    const float* x   = (const float*)d_in[0];
    const int*   ei  = (const int*)d_in[1];     // int32! (JAX x64 disabled)
    const float* W   = (const float*)d_in[2];
    const float* b   = (const float*)d_in[3];
    float*       out = (float*)d_out;

    int N = in_sizes[0] / D;       // 100000
    int E = in_sizes[1] / 2;       // 1600000

    int nslots = N * NNB;
    k_init<<<(nslots + 255) / 256, 256>>>(nslots);
    k_insert<<<(E + 255) / 256, 256>>>(ei, E);
    k_agg_gemm<<<(N + BN - 1) / BN, 256>>>(x, ei, W, b, out, N, E);
}